// round 7
// baseline (speedup 1.0000x reference)
#include <cuda_runtime.h>
#include <math.h>

#define NB 2
#define NQ 4
#define NH 32
#define NHK 8
#define HD 128
#define DMODEL 4096
#define NCOLS (DMODEL + 1024 + 1024)   // 6144 fused qkv output columns
#define NROWS (NB * NQ)                // 8
#define SMAX 4352
#define NROWS_ATT (NB * NH * NQ)       // 256
#define KSPLIT 64
#define KCH (DMODEL / KSPLIT)          // 64
#define VSPLIT 8
#define TS 64                          // draft tile: key rows per block
#define KPAD 132                       // padded K-tile row

// vector reduction: 4x fewer L2 atomics than scalar atomicAdd
__device__ __forceinline__ void red_add_v4(float* p, float4 v) {
    asm volatile("red.global.add.v4.f32 [%0], {%1,%2,%3,%4};"
                 :: "l"(p), "f"(v.x), "f"(v.y), "f"(v.z), "f"(v.w) : "memory");
}

// ---------------- scratch (device globals; no allocation) ----------------
__device__ float g_qkv[NROWS * NCOLS];
__device__ float g_cos[SMAX * 64];
__device__ float g_sin[SMAX * 64];
__device__ float g_qr[NB * NH * NQ * HD];
__device__ float g_knew[NB * NHK * NQ * HD];
__device__ float g_vnew[NB * NHK * NQ * HD];
__device__ float g_draft[NROWS_ATT * SMAX];
__device__ unsigned int g_thrkey[NROWS_ATT];
__device__ float g_rowmax[NROWS_ATT];
__device__ float g_num[NROWS_ATT * HD];
__device__ float g_den[NROWS_ATT];

// ---------------- init: zero accumulators + rope tables in one kernel ----------------
__global__ void init_kernel(float* __restrict__ out, int osz, int zb, int S) {
    if ((int)blockIdx.x < zb) {
        int i = blockIdx.x * 256 + threadIdx.x;
        if (i < NROWS * NCOLS)   g_qkv[i] = 0.f;
        if (i < NROWS_ATT * HD)  g_num[i] = 0.f;
        if (i < NROWS_ATT)       g_den[i] = 0.f;
        if (i < osz)             out[i]  = 0.f;
        return;
    }
    __shared__ float invf[64];
    int t = threadIdx.x;
    if (t < 64) {
        double x = (double)t / 64.0;
        double p = exp(x * 9.210340371976184);   // ln(10000)
        invf[t] = 1.0f / (float)p;
    }
    __syncthreads();
    int pos = (blockIdx.x - zb) * 4 + (t >> 6);
    int i = t & 63;
    if (pos < S) {
        float arg = (float)pos * invf[i];
        double a = (double)arg;
        double k = rint(a * 0.15915494309189535);
        float r = (float)(a - k * 6.283185307179586);
        float s, c;
        __sincosf(r, &s, &c);
        g_cos[pos * 64 + i] = c;
        g_sin[pos * 64 + i] = s;
    }
}

// ---------------- fused QKV projection: 4 cols/thread, KSPLIT=64 ----------------
// grid: (NCOLS/1024, KSPLIT), block 256
__global__ void __launch_bounds__(256) proj_qkv(const float* __restrict__ hid,
                                                const float* __restrict__ Wq,
                                                const float* __restrict__ Wk,
                                                const float* __restrict__ Wv) {
    __shared__ float hs[NROWS][KCH];
    int t = threadIdx.x;
    int j = (blockIdx.x * 256 + t) * 4;
    int k0 = blockIdx.y * KCH;
    if (t < NROWS * KCH / 4) {
        int r = t / (KCH / 4), c4 = t % (KCH / 4);
        *(float4*)&hs[r][c4 * 4] = *(const float4*)&hid[r * DMODEL + k0 + c4 * 4];
    }
    __syncthreads();

    const float* W; int ncol; int jj;
    if (j < DMODEL)             { W = Wq; ncol = DMODEL; jj = j; }
    else if (j < DMODEL + 1024) { W = Wk; ncol = 1024;   jj = j - DMODEL; }
    else                        { W = Wv; ncol = 1024;   jj = j - DMODEL - 1024; }

    float4 acc[NROWS];
#pragma unroll
    for (int r = 0; r < NROWS; r++) acc[r] = make_float4(0.f, 0.f, 0.f, 0.f);
    const float* wp = W + (size_t)k0 * ncol + jj;
#pragma unroll 8
    for (int k = 0; k < KCH; k++) {
        float4 w4 = *(const float4*)(wp + (size_t)k * ncol);
#pragma unroll
        for (int r = 0; r < NROWS; r++) {
            float h = hs[r][k];
            acc[r].x += h * w4.x; acc[r].y += h * w4.y;
            acc[r].z += h * w4.z; acc[r].w += h * w4.w;
        }
    }
#pragma unroll
    for (int r = 0; r < NROWS; r++)
        red_add_v4(&g_qkv[r * NCOLS + j], acc[r]);
}

// ---------------- rope new q/k, copy v (float4 pair tasks) ----------------
// tasks = NB*NH*NQ*16 = 4096 -> 16 blocks x 256
__global__ void rope_qkv(int S) {
    int idx = blockIdx.x * 256 + threadIdx.x;
    int c = (idx & 15) * 4;
    int q = (idx >> 4) & 3;
    int h = (idx >> 6) & 31;
    int b = idx >> 11;
    int pos = S - NQ + q;
    int row = b * NQ + q;
    float4 cv = *(const float4*)&g_cos[pos * 64 + c];
    float4 sv = *(const float4*)&g_sin[pos * 64 + c];
    const float* base = g_qkv + row * NCOLS;
    {
        float4 xl = *(const float4*)(base + h * HD + c);
        float4 xh = *(const float4*)(base + h * HD + c + 64);
        float4 lo, hi;
        lo.x = xl.x * cv.x - xh.x * sv.x;  hi.x = xh.x * cv.x + xl.x * sv.x;
        lo.y = xl.y * cv.y - xh.y * sv.y;  hi.y = xh.y * cv.y + xl.y * sv.y;
        lo.z = xl.z * cv.z - xh.z * sv.z;  hi.z = xh.z * cv.z + xl.z * sv.z;
        lo.w = xl.w * cv.w - xh.w * sv.w;  hi.w = xh.w * cv.w + xl.w * sv.w;
        float* qo = g_qr + ((b * NH + h) * NQ + q) * HD;
        *(float4*)(qo + c) = lo; *(float4*)(qo + c + 64) = hi;
    }
    if (h < NHK) {
        const float* kb = base + DMODEL + h * HD;
        float4 xl = *(const float4*)(kb + c);
        float4 xh = *(const float4*)(kb + c + 64);
        float4 lo, hi;
        lo.x = xl.x * cv.x - xh.x * sv.x;  hi.x = xh.x * cv.x + xl.x * sv.x;
        lo.y = xl.y * cv.y - xh.y * sv.y;  hi.y = xh.y * cv.y + xl.y * sv.y;
        lo.z = xl.z * cv.z - xh.z * sv.z;  hi.z = xh.z * cv.z + xl.z * sv.z;
        lo.w = xl.w * cv.w - xh.w * sv.w;  hi.w = xh.w * cv.w + xl.w * sv.w;
        float* ko = g_knew + ((b * NHK + h) * NQ + q) * HD;
        *(float4*)(ko + c) = lo; *(float4*)(ko + c + 64) = hi;
        const float* vb = base + DMODEL + 1024 + h * HD;
        float* vo = g_vnew + ((b * NHK + h) * NQ + q) * HD;
        *(float4*)(vo + c)      = *(const float4*)(vb + c);
        *(float4*)(vo + c + 64) = *(const float4*)(vb + c + 64);
    }
}

// ---------------- draft scores: quarter-row split, K in registers for 4 q dots ----------------
// grid: (ceil(S/TS), NB*NH), block 256 = 64 rows x 4 quarters
__global__ void __launch_bounds__(256) draft_kernel(const float* __restrict__ kcache,
                                                    int S, int KV) {
    __shared__ float ks[TS][KPAD];
    __shared__ float qsf[NQ * HD];
    int bh = blockIdx.y;
    int b = bh >> 5, h = bh & 31;
    int s0 = blockIdx.x * TS;
    int t = threadIdx.x;

    if (t < 128)
        *(float4*)&qsf[t * 4] = *(const float4*)&g_qr[(size_t)bh * NQ * HD + t * 4];

    // load + rope K tile: 1024 float4-pair tasks over 256 threads
    for (int task = t; task < TS * 16; task += 256) {
        int r = task >> 4, c = (task & 15) * 4;
        int s = s0 + r;
        if (s >= S) continue;
        float4 lo, hi;
        if (s < KV) {
            const float* kp = kcache + ((size_t)bh * KV + s) * HD;
            float4 xl = *(const float4*)(kp + c);
            float4 xh = *(const float4*)(kp + c + 64);
            float4 cv = *(const float4*)&g_cos[s * 64 + c];
            float4 sv = *(const float4*)&g_sin[s * 64 + c];
            lo.x = xl.x * cv.x - xh.x * sv.x;  hi.x = xh.x * cv.x + xl.x * sv.x;
            lo.y = xl.y * cv.y - xh.y * sv.y;  hi.y = xh.y * cv.y + xl.y * sv.y;
            lo.z = xl.z * cv.z - xh.z * sv.z;  hi.z = xh.z * cv.z + xl.z * sv.z;
            lo.w = xl.w * cv.w - xh.w * sv.w;  hi.w = xh.w * cv.w + xl.w * sv.w;
        } else {
            const float* kp = g_knew + (((b * NHK + (h >> 2)) * NQ) + (s - KV)) * HD;
            lo = *(const float4*)(kp + c);
            hi = *(const float4*)(kp + c + 64);
        }
        *(float4*)&ks[r][c] = lo;
        *(float4*)&ks[r][c + 64] = hi;
    }
    __syncthreads();

    // thread -> (row sl = t>>2, quarter = t&3). K quarter loaded once into regs,
    // reused for all 4 q dots; partial sums combined across quarters via shfl.
    int sl = t >> 2, quar = t & 3;
    int base = quar * 32;
    int s = s0 + sl;
    float acc[NQ] = {0.f, 0.f, 0.f, 0.f};
    if (s < S) {
        const float* kr = &ks[sl][base];
#pragma unroll
        for (int k = 0; k < 32; k += 4) {
            float4 kv = *(const float4*)(kr + k);
#pragma unroll
            for (int q = 0; q < NQ; q++) {
                float4 qv = *(const float4*)&qsf[q * HD + base + k];
                acc[q] += kv.x * qv.x + kv.y * qv.y + kv.z * qv.z + kv.w * qv.w;
            }
        }
    }
#pragma unroll
    for (int q = 0; q < NQ; q++) {
        acc[q] += __shfl_xor_sync(0xffffffffu, acc[q], 1);
        acc[q] += __shfl_xor_sync(0xffffffffu, acc[q], 2);
    }
    if (quar == 0 && s < S) {
#pragma unroll
        for (int q = 0; q < NQ; q++)
            g_draft[(size_t)(bh * NQ + q) * S + s] = acc[q];
    }
}

// ---------------- per-row top-k threshold: 4-level radix select ----------------
__global__ void __launch_bounds__(256) topk_thresh(int S, int nrem) {
    __shared__ unsigned int keys[SMAX];
    __shared__ int hist[256];
    __shared__ float wmax[8];
    __shared__ unsigned int s_prefix;
    __shared__ int s_need;
    int row = blockIdx.x;
    const float* dr = &g_draft[(size_t)row * S];
    int t = threadIdx.x, lane = t & 31, warp = t >> 5;

    float mx = -3.4e38f;
    for (int i = t; i < S; i += 256) {
        float v = dr[i];
        mx = fmaxf(mx, v);
        unsigned int u = __float_as_uint(v);
        keys[i] = (u & 0x80000000u) ? ~u : (u | 0x80000000u);
    }
#pragma unroll
    for (int o = 16; o; o >>= 1) mx = fmaxf(mx, __shfl_xor_sync(0xffffffffu, mx, o));
    if (lane == 0) wmax[warp] = mx;
    __syncthreads();
    if (t == 0) {
        float m = wmax[0];
#pragma unroll
        for (int w = 1; w < 8; w++) m = fmaxf(m, wmax[w]);
        g_rowmax[row] = m;
    }

    unsigned int prefix = 0u;
    int need = nrem;
    for (int level = 3; level >= 0; level--) {
        hist[t] = 0;
        __syncthreads();
        int shift = level * 8;
        unsigned int pmask = (level == 3) ? 0u : (0xFFFFFFFFu << (shift + 8));
        for (int i = t; i < S; i += 256) {
            unsigned int k = keys[i];
            if ((k & pmask) == prefix) atomicAdd(&hist[(k >> shift) & 255], 1);
        }
        __syncthreads();
        if (t == 0) {
            int cum = 0, d = 255;
            for (; d > 0; d--) { cum += hist[d]; if (cum >= need) break; }
            if (cum < need) { cum += hist[0]; d = 0; }
            s_need = need - (cum - hist[d]);
            s_prefix = prefix | ((unsigned int)d << shift);
        }
        __syncthreads();
        prefix = s_prefix; need = s_need;
        __syncthreads();
    }
    if (t == 0) g_thrkey[row] = prefix;
}

// ---------------- sparse softmax * V gather (float4, 8 i-groups) ----------------
// grid: (NROWS_ATT, VSPLIT), block 256 = 8 groups x 32 lanes
__global__ void __launch_bounds__(256) attn_gather(const float* __restrict__ vcache,
                                                   int S, int KV) {
    __shared__ int sidx[512];
    __shared__ float sw[512];
    __shared__ int cnt;
    __shared__ float4 sacc[8][32];
    __shared__ float wden[8];
    int row = blockIdx.x;
    int bh = row >> 2;
    int b = bh >> 5, h = bh & 31;
    int chunk = (S + VSPLIT - 1) / VSPLIT;
    int s0 = blockIdx.y * chunk;
    int s1 = min(S, s0 + chunk);
    int t = threadIdx.x;
    if (t == 0) cnt = 0;
    __syncthreads();

    unsigned int thr = g_thrkey[row];
    float mx = g_rowmax[row];
    const float* dr = &g_draft[(size_t)row * S];
    for (int s = s0 + t; s < s1; s += 256) {
        float v = dr[s];
        unsigned int u = __float_as_uint(v);
        unsigned int key = (u & 0x80000000u) ? ~u : (u | 0x80000000u);
        if (key >= thr) {
            int p = atomicAdd(&cnt, 1);
            if (p < 512) {
                sidx[p] = s;
                sw[p] = __expf((v - mx) * 0.08838834764831843f);  // 1/sqrt(128)
            }
        }
    }
    __syncthreads();
    int n = min(cnt, 512);
    int hk = h >> 2;
    int g = t >> 5, lane = t & 31;
    float4 acc = make_float4(0.f, 0.f, 0.f, 0.f);
    for (int i = g; i < n; i += 8) {
        int s = sidx[i];
        float w = sw[i];
        const float* vp = (s < KV)
            ? &vcache[((size_t)bh * KV + s) * HD]
            : &g_vnew[(((b * NHK + hk) * NQ) + (s - KV)) * HD];
        float4 v4 = *(const float4*)(vp + lane * 4);
        acc.x += w * v4.x; acc.y += w * v4.y;
        acc.z += w * v4.z; acc.w += w * v4.w;
    }
    sacc[g][lane] = acc;
    __syncthreads();
    if (t < 32) {
        float4 sum = sacc[0][t];
#pragma unroll
        for (int gg = 1; gg < 8; gg++) {
            float4 a = sacc[gg][t];
            sum.x += a.x; sum.y += a.y; sum.z += a.z; sum.w += a.w;
        }
        red_add_v4(&g_num[row * HD + t * 4], sum);
    }

    float dsum = 0.f;
    for (int i = t; i < n; i += 256) dsum += sw[i];
#pragma unroll
    for (int o = 16; o; o >>= 1) dsum += __shfl_xor_sync(0xffffffffu, dsum, o);
    if ((t & 31) == 0) wden[t >> 5] = dsum;
    __syncthreads();
    if (t == 0) {
        float s8 = 0.f;
#pragma unroll
        for (int w = 0; w < 8; w++) s8 += wden[w];
        atomicAdd(&g_den[row], s8);
    }
}

// ---------------- output projection (finalize fused into tile load) ----------------
// grid: (DMODEL/1024, KSPLIT), block 256, 4 cols/thread
__global__ void __launch_bounds__(256) proj_out(const float* __restrict__ Wo,
                                                float* __restrict__ out) {
    __shared__ float hs[NROWS][KCH];
    int t = threadIdx.x;
    int j = (blockIdx.x * 256 + t) * 4;
    int k0 = blockIdx.y * KCH;
    if (t < NROWS * KCH / 4) {
        int r = t / (KCH / 4);              // r = b*NQ + q
        int kg = k0 + (t % (KCH / 4)) * 4;
        int b = r >> 2, q = r & 3;
        int h = kg >> 7, d = kg & 127;
        int row2 = ((b * NH + h) * NQ + q);
        float4 v = *(const float4*)&g_num[row2 * HD + d];
        float inv = 1.0f / g_den[row2];
        v.x *= inv; v.y *= inv; v.z *= inv; v.w *= inv;
        *(float4*)&hs[r][kg - k0] = v;
    }
    __syncthreads();

    float4 acc[NROWS];
#pragma unroll
    for (int r = 0; r < NROWS; r++) acc[r] = make_float4(0.f, 0.f, 0.f, 0.f);
    const float* wp = Wo + (size_t)k0 * DMODEL + j;
#pragma unroll 8
    for (int k = 0; k < KCH; k++) {
        float4 w4 = *(const float4*)(wp + (size_t)k * DMODEL);
#pragma unroll
        for (int r = 0; r < NROWS; r++) {
            float h = hs[r][k];
            acc[r].x += h * w4.x; acc[r].y += h * w4.y;
            acc[r].z += h * w4.z; acc[r].w += h * w4.w;
        }
    }
#pragma unroll
    for (int r = 0; r < NROWS; r++)
        red_add_v4(&out[r * DMODEL + j], acc[r]);
}

// ---------------- launcher ----------------
extern "C" void kernel_launch(void* const* d_in, const int* in_sizes, int n_in,
                              void* d_out, int out_size) {
    const float* hid    = (const float*)d_in[0];
    const float* kcache = (const float*)d_in[1];
    const float* vcache = (const float*)d_in[2];
    const float* Wq     = (const float*)d_in[3];
    const float* Wk     = (const float*)d_in[4];
    const float* Wv     = (const float*)d_in[5];
    const float* Wo     = (const float*)d_in[6];
    float* out = (float*)d_out;

    int KV = in_sizes[1] / (NB * NH * HD);
    int S = KV + NQ;
    if (S > SMAX) S = SMAX;
    int mo = S - (int)((double)S * 0.9);
    int cap = (S < 128) ? S : 128;
    int nrem = (cap > mo) ? cap : mo;
    if (nrem > 500) nrem = 500;

    int zmax = NROWS * NCOLS;
    if (out_size > zmax) zmax = out_size;
    int zb = (zmax + 255) / 256;
    int rb = (S + 3) / 4;
    init_kernel<<<zb + rb, 256>>>(out, out_size, zb, S);
    proj_qkv<<<dim3(NCOLS / 1024, KSPLIT), 256>>>(hid, Wq, Wk, Wv);
    rope_qkv<<<16, 256>>>(S);
    draft_kernel<<<dim3((S + TS - 1) / TS, NB * NH), 256>>>(kcache, S, KV);
    topk_thresh<<<NROWS_ATT, 256>>>(S, nrem);
    attn_gather<<<dim3(NROWS_ATT, VSPLIT), 256>>>(vcache, S, KV);
    proj_out<<<dim3(DMODEL / 1024, KSPLIT), 256>>>(Wo, out);
}

// round 13
// speedup vs baseline: 1.7794x; 1.7794x over previous
#include <cuda_runtime.h>
#include <math.h>

#define NB 2
#define NQ 4
#define NH 32
#define NHK 8
#define HD 128
#define DMODEL 4096
#define NCOLS (DMODEL + 1024 + 1024)   // 6144 fused qkv output columns
#define NROWS (NB * NQ)                // 8
#define SMAX 4352
#define NROWS_ATT (NB * NH * NQ)       // 256
#define KSPLIT 64
#define KCH (DMODEL / KSPLIT)          // 64
#define VSPLIT 8
#define DITER 4                        // draft: key rows per warp

// vector reduction: 4x fewer L2 atomics than scalar atomicAdd
__device__ __forceinline__ void red_add_v4(float* p, float4 v) {
    asm volatile("red.global.add.v4.f32 [%0], {%1,%2,%3,%4};"
                 :: "l"(p), "f"(v.x), "f"(v.y), "f"(v.z), "f"(v.w) : "memory");
}

// ---------------- scratch (device globals; no allocation) ----------------
__device__ float g_qkv[NROWS * NCOLS];
__device__ float g_cos[SMAX * 64];
__device__ float g_sin[SMAX * 64];
__device__ float g_qr[NB * NH * NQ * HD];
__device__ float g_knew[NB * NHK * NQ * HD];
__device__ float g_vnew[NB * NHK * NQ * HD];
__device__ float g_draft[NROWS_ATT * SMAX];
__device__ unsigned int g_thrkey[NROWS_ATT];
__device__ float g_rowmax[NROWS_ATT];
__device__ float g_num[NROWS_ATT * HD];
__device__ float g_den[NROWS_ATT];

// ---------------- init: zero accumulators + rope tables in one kernel ----------------
__global__ void init_kernel(float* __restrict__ out, int osz, int zb, int S) {
    if ((int)blockIdx.x < zb) {
        int i = blockIdx.x * 256 + threadIdx.x;
        if (i < NROWS * NCOLS)   g_qkv[i] = 0.f;
        if (i < NROWS_ATT * HD)  g_num[i] = 0.f;
        if (i < NROWS_ATT)       g_den[i] = 0.f;
        if (i < osz)             out[i]  = 0.f;
        return;
    }
    __shared__ float invf[64];
    int t = threadIdx.x;
    if (t < 64) {
        double x = (double)t / 64.0;
        double p = exp(x * 9.210340371976184);   // ln(10000)
        invf[t] = 1.0f / (float)p;
    }
    __syncthreads();
    int pos = (blockIdx.x - zb) * 4 + (t >> 6);
    int i = t & 63;
    if (pos < S) {
        float arg = (float)pos * invf[i];
        double a = (double)arg;
        double k = rint(a * 0.15915494309189535);
        float r = (float)(a - k * 6.283185307179586);
        float s, c;
        __sincosf(r, &s, &c);
        g_cos[pos * 64 + i] = c;
        g_sin[pos * 64 + i] = s;
    }
}

// ---------------- fused QKV projection: 4 cols/thread, KSPLIT=64 ----------------
// grid: (NCOLS/1024, KSPLIT), block 256
__global__ void __launch_bounds__(256) proj_qkv(const float* __restrict__ hid,
                                                const float* __restrict__ Wq,
                                                const float* __restrict__ Wk,
                                                const float* __restrict__ Wv) {
    __shared__ float hs[NROWS][KCH];
    int t = threadIdx.x;
    int j = (blockIdx.x * 256 + t) * 4;
    int k0 = blockIdx.y * KCH;
    if (t < NROWS * KCH / 4) {
        int r = t / (KCH / 4), c4 = t % (KCH / 4);
        *(float4*)&hs[r][c4 * 4] = *(const float4*)&hid[r * DMODEL + k0 + c4 * 4];
    }
    __syncthreads();

    const float* W; int ncol; int jj;
    if (j < DMODEL)             { W = Wq; ncol = DMODEL; jj = j; }
    else if (j < DMODEL + 1024) { W = Wk; ncol = 1024;   jj = j - DMODEL; }
    else                        { W = Wv; ncol = 1024;   jj = j - DMODEL - 1024; }

    float4 acc[NROWS];
#pragma unroll
    for (int r = 0; r < NROWS; r++) acc[r] = make_float4(0.f, 0.f, 0.f, 0.f);
    const float* wp = W + (size_t)k0 * ncol + jj;
#pragma unroll 8
    for (int k = 0; k < KCH; k++) {
        float4 w4 = *(const float4*)(wp + (size_t)k * ncol);
#pragma unroll
        for (int r = 0; r < NROWS; r++) {
            float h = hs[r][k];
            acc[r].x += h * w4.x; acc[r].y += h * w4.y;
            acc[r].z += h * w4.z; acc[r].w += h * w4.w;
        }
    }
#pragma unroll
    for (int r = 0; r < NROWS; r++)
        red_add_v4(&g_qkv[r * NCOLS + j], acc[r]);
}

// ---------------- rope new q/k, copy v (float4 pair tasks) ----------------
// tasks = NB*NH*NQ*16 = 4096 -> 16 blocks x 256
__global__ void rope_qkv(int S) {
    int idx = blockIdx.x * 256 + threadIdx.x;
    int c = (idx & 15) * 4;
    int q = (idx >> 4) & 3;
    int h = (idx >> 6) & 31;
    int b = idx >> 11;
    int pos = S - NQ + q;
    int row = b * NQ + q;
    float4 cv = *(const float4*)&g_cos[pos * 64 + c];
    float4 sv = *(const float4*)&g_sin[pos * 64 + c];
    const float* base = g_qkv + row * NCOLS;
    {
        float4 xl = *(const float4*)(base + h * HD + c);
        float4 xh = *(const float4*)(base + h * HD + c + 64);
        float4 lo, hi;
        lo.x = xl.x * cv.x - xh.x * sv.x;  hi.x = xh.x * cv.x + xl.x * sv.x;
        lo.y = xl.y * cv.y - xh.y * sv.y;  hi.y = xh.y * cv.y + xl.y * sv.y;
        lo.z = xl.z * cv.z - xh.z * sv.z;  hi.z = xh.z * cv.z + xl.z * sv.z;
        lo.w = xl.w * cv.w - xh.w * sv.w;  hi.w = xh.w * cv.w + xl.w * sv.w;
        float* qo = g_qr + ((b * NH + h) * NQ + q) * HD;
        *(float4*)(qo + c) = lo; *(float4*)(qo + c + 64) = hi;
    }
    if (h < NHK) {
        const float* kb = base + DMODEL + h * HD;
        float4 xl = *(const float4*)(kb + c);
        float4 xh = *(const float4*)(kb + c + 64);
        float4 lo, hi;
        lo.x = xl.x * cv.x - xh.x * sv.x;  hi.x = xh.x * cv.x + xl.x * sv.x;
        lo.y = xl.y * cv.y - xh.y * sv.y;  hi.y = xh.y * cv.y + xl.y * sv.y;
        lo.z = xl.z * cv.z - xh.z * sv.z;  hi.z = xh.z * cv.z + xl.z * sv.z;
        lo.w = xl.w * cv.w - xh.w * sv.w;  hi.w = xh.w * cv.w + xl.w * sv.w;
        float* ko = g_knew + ((b * NHK + h) * NQ + q) * HD;
        *(float4*)(ko + c) = lo; *(float4*)(ko + c + 64) = hi;
        const float* vb = base + DMODEL + 1024 + h * HD;
        float* vo = g_vnew + ((b * NHK + h) * NQ + q) * HD;
        *(float4*)(vo + c)      = *(const float4*)(vb + c);
        *(float4*)(vo + c + 64) = *(const float4*)(vb + c + 64);
    }
}

// ---------------- draft scores: warp-per-key-row, all-register (no shared K) ----------------
// grid: (ceil(S/(8*DITER)), NB*NH), block 256 = 8 warps
__global__ void __launch_bounds__(256) draft_kernel(const float* __restrict__ kcache,
                                                    int S, int KV) {
    int bh = blockIdx.y;
    int b = bh >> 5, h = bh & 31;
    int lane = threadIdx.x & 31, warp = threadIdx.x >> 5;

    // q in registers: lane l holds q[q][4l..4l+3]
    float4 qreg[NQ];
    const float* qp = &g_qr[(size_t)bh * NQ * HD + lane * 4];
#pragma unroll
    for (int q = 0; q < NQ; q++) qreg[q] = *(const float4*)(qp + q * HD);

    int sbase = blockIdx.x * (8 * DITER) + warp;
#pragma unroll
    for (int it = 0; it < DITER; it++) {
        int s = sbase + it * 8;
        if (s >= S) break;                 // warp-uniform exit
        float4 kr;
        if (s < KV) {
            float4 x = *(const float4*)&kcache[((size_t)bh * KV + s) * HD + lane * 4];
            float4 cv = *(const float4*)&g_cos[s * 64 + (lane & 15) * 4];
            float4 sv = *(const float4*)&g_sin[s * 64 + (lane & 15) * 4];
            float sign = (lane < 16) ? -1.f : 1.f;
            float ox = __shfl_xor_sync(0xffffffffu, x.x, 16);
            float oy = __shfl_xor_sync(0xffffffffu, x.y, 16);
            float oz = __shfl_xor_sync(0xffffffffu, x.z, 16);
            float ow = __shfl_xor_sync(0xffffffffu, x.w, 16);
            kr.x = x.x * cv.x + sign * ox * sv.x;
            kr.y = x.y * cv.y + sign * oy * sv.y;
            kr.z = x.z * cv.z + sign * oz * sv.z;
            kr.w = x.w * cv.w + sign * ow * sv.w;
        } else {
            kr = *(const float4*)&g_knew[(((b * NHK + (h >> 2)) * NQ) + (s - KV)) * HD + lane * 4];
        }
        float a0 = kr.x * qreg[0].x + kr.y * qreg[0].y + kr.z * qreg[0].z + kr.w * qreg[0].w;
        float a1 = kr.x * qreg[1].x + kr.y * qreg[1].y + kr.z * qreg[1].z + kr.w * qreg[1].w;
        float a2 = kr.x * qreg[2].x + kr.y * qreg[2].y + kr.z * qreg[2].z + kr.w * qreg[2].w;
        float a3 = kr.x * qreg[3].x + kr.y * qreg[3].y + kr.z * qreg[3].z + kr.w * qreg[3].w;
#pragma unroll
        for (int o = 16; o; o >>= 1) {
            a0 += __shfl_xor_sync(0xffffffffu, a0, o);
            a1 += __shfl_xor_sync(0xffffffffu, a1, o);
            a2 += __shfl_xor_sync(0xffffffffu, a2, o);
            a3 += __shfl_xor_sync(0xffffffffu, a3, o);
        }
        if (lane == 0) {
            float* dp = &g_draft[(size_t)(bh * NQ) * S + s];
            dp[0]                 = a0;
            dp[(size_t)S]         = a1;
            dp[(size_t)S * 2]     = a2;
            dp[(size_t)S * 3]     = a3;
        }
    }
}

// ---------------- per-row top-k threshold: 4-level radix select ----------------
__global__ void __launch_bounds__(256) topk_thresh(int S, int nrem) {
    __shared__ unsigned int keys[SMAX];
    __shared__ int hist[256];
    __shared__ float wmax[8];
    __shared__ unsigned int s_prefix;
    __shared__ int s_need;
    int row = blockIdx.x;
    const float* dr = &g_draft[(size_t)row * S];
    int t = threadIdx.x, lane = t & 31, warp = t >> 5;

    float mx = -3.4e38f;
    for (int i = t; i < S; i += 256) {
        float v = dr[i];
        mx = fmaxf(mx, v);
        unsigned int u = __float_as_uint(v);
        keys[i] = (u & 0x80000000u) ? ~u : (u | 0x80000000u);
    }
#pragma unroll
    for (int o = 16; o; o >>= 1) mx = fmaxf(mx, __shfl_xor_sync(0xffffffffu, mx, o));
    if (lane == 0) wmax[warp] = mx;
    __syncthreads();
    if (t == 0) {
        float m = wmax[0];
#pragma unroll
        for (int w = 1; w < 8; w++) m = fmaxf(m, wmax[w]);
        g_rowmax[row] = m;
    }

    unsigned int prefix = 0u;
    int need = nrem;
    for (int level = 3; level >= 0; level--) {
        hist[t] = 0;
        __syncthreads();
        int shift = level * 8;
        unsigned int pmask = (level == 3) ? 0u : (0xFFFFFFFFu << (shift + 8));
        for (int i = t; i < S; i += 256) {
            unsigned int k = keys[i];
            if ((k & pmask) == prefix) atomicAdd(&hist[(k >> shift) & 255], 1);
        }
        __syncthreads();
        if (t == 0) {
            int cum = 0, d = 255;
            for (; d > 0; d--) { cum += hist[d]; if (cum >= need) break; }
            if (cum < need) { cum += hist[0]; d = 0; }
            s_need = need - (cum - hist[d]);
            s_prefix = prefix | ((unsigned int)d << shift);
        }
        __syncthreads();
        prefix = s_prefix; need = s_need;
        __syncthreads();
    }
    if (t == 0) g_thrkey[row] = prefix;
}

// ---------------- sparse softmax * V gather (float4, 8 i-groups) ----------------
// grid: (NROWS_ATT, VSPLIT), block 256 = 8 groups x 32 lanes
__global__ void __launch_bounds__(256) attn_gather(const float* __restrict__ vcache,
                                                   int S, int KV) {
    __shared__ int sidx[512];
    __shared__ float sw[512];
    __shared__ int cnt;
    __shared__ float4 sacc[8][32];
    __shared__ float wden[8];
    int row = blockIdx.x;
    int bh = row >> 2;
    int b = bh >> 5, h = bh & 31;
    int chunk = (S + VSPLIT - 1) / VSPLIT;
    int s0 = blockIdx.y * chunk;
    int s1 = min(S, s0 + chunk);
    int t = threadIdx.x;
    if (t == 0) cnt = 0;
    __syncthreads();

    unsigned int thr = g_thrkey[row];
    float mx = g_rowmax[row];
    const float* dr = &g_draft[(size_t)row * S];
    for (int s = s0 + t; s < s1; s += 256) {
        float v = dr[s];
        unsigned int u = __float_as_uint(v);
        unsigned int key = (u & 0x80000000u) ? ~u : (u | 0x80000000u);
        if (key >= thr) {
            int p = atomicAdd(&cnt, 1);
            if (p < 512) {
                sidx[p] = s;
                sw[p] = __expf((v - mx) * 0.08838834764831843f);  // 1/sqrt(128)
            }
        }
    }
    __syncthreads();
    int n = min(cnt, 512);
    int hk = h >> 2;
    int g = t >> 5, lane = t & 31;
    float4 acc = make_float4(0.f, 0.f, 0.f, 0.f);
    for (int i = g; i < n; i += 8) {
        int s = sidx[i];
        float w = sw[i];
        const float* vp = (s < KV)
            ? &vcache[((size_t)bh * KV + s) * HD]
            : &g_vnew[(((b * NHK + hk) * NQ) + (s - KV)) * HD];
        float4 v4 = *(const float4*)(vp + lane * 4);
        acc.x += w * v4.x; acc.y += w * v4.y;
        acc.z += w * v4.z; acc.w += w * v4.w;
    }
    sacc[g][lane] = acc;
    __syncthreads();
    if (t < 32) {
        float4 sum = sacc[0][t];
#pragma unroll
        for (int gg = 1; gg < 8; gg++) {
            float4 a = sacc[gg][t];
            sum.x += a.x; sum.y += a.y; sum.z += a.z; sum.w += a.w;
        }
        red_add_v4(&g_num[row * HD + t * 4], sum);
    }

    float dsum = 0.f;
    for (int i = t; i < n; i += 256) dsum += sw[i];
#pragma unroll
    for (int o = 16; o; o >>= 1) dsum += __shfl_xor_sync(0xffffffffu, dsum, o);
    if ((t & 31) == 0) wden[t >> 5] = dsum;
    __syncthreads();
    if (t == 0) {
        float s8 = 0.f;
#pragma unroll
        for (int w = 0; w < 8; w++) s8 += wden[w];
        atomicAdd(&g_den[row], s8);
    }
}

// ---------------- output projection (finalize fused into tile load) ----------------
// grid: (DMODEL/1024, KSPLIT), block 256, 4 cols/thread
__global__ void __launch_bounds__(256) proj_out(const float* __restrict__ Wo,
                                                float* __restrict__ out) {
    __shared__ float hs[NROWS][KCH];
    int t = threadIdx.x;
    int j = (blockIdx.x * 256 + t) * 4;
    int k0 = blockIdx.y * KCH;
    if (t < NROWS * KCH / 4) {
        int r = t / (KCH / 4);              // r = b*NQ + q
        int kg = k0 + (t % (KCH / 4)) * 4;
        int b = r >> 2, q = r & 3;
        int h = kg >> 7, d = kg & 127;
        int row2 = ((b * NH + h) * NQ + q);
        float4 v = *(const float4*)&g_num[row2 * HD + d];
        float inv = 1.0f / g_den[row2];
        v.x *= inv; v.y *= inv; v.z *= inv; v.w *= inv;
        *(float4*)&hs[r][kg - k0] = v;
    }
    __syncthreads();

    float4 acc[NROWS];
#pragma unroll
    for (int r = 0; r < NROWS; r++) acc[r] = make_float4(0.f, 0.f, 0.f, 0.f);
    const float* wp = Wo + (size_t)k0 * DMODEL + j;
#pragma unroll 8
    for (int k = 0; k < KCH; k++) {
        float4 w4 = *(const float4*)(wp + (size_t)k * DMODEL);
#pragma unroll
        for (int r = 0; r < NROWS; r++) {
            float h = hs[r][k];
            acc[r].x += h * w4.x; acc[r].y += h * w4.y;
            acc[r].z += h * w4.z; acc[r].w += h * w4.w;
        }
    }
#pragma unroll
    for (int r = 0; r < NROWS; r++)
        red_add_v4(&out[r * DMODEL + j], acc[r]);
}

// ---------------- launcher ----------------
extern "C" void kernel_launch(void* const* d_in, const int* in_sizes, int n_in,
                              void* d_out, int out_size) {
    const float* hid    = (const float*)d_in[0];
    const float* kcache = (const float*)d_in[1];
    const float* vcache = (const float*)d_in[2];
    const float* Wq     = (const float*)d_in[3];
    const float* Wk     = (const float*)d_in[4];
    const float* Wv     = (const float*)d_in[5];
    const float* Wo     = (const float*)d_in[6];
    float* out = (float*)d_out;

    int KV = in_sizes[1] / (NB * NH * HD);
    int S = KV + NQ;
    if (S > SMAX) S = SMAX;
    int mo = S - (int)((double)S * 0.9);
    int cap = (S < 128) ? S : 128;
    int nrem = (cap > mo) ? cap : mo;
    if (nrem > 500) nrem = 500;

    int zmax = NROWS * NCOLS;
    if (out_size > zmax) zmax = out_size;
    int zb = (zmax + 255) / 256;
    int rb = (S + 3) / 4;
    init_kernel<<<zb + rb, 256>>>(out, out_size, zb, S);
    proj_qkv<<<dim3(NCOLS / 1024, KSPLIT), 256>>>(hid, Wq, Wk, Wv);
    rope_qkv<<<16, 256>>>(S);
    draft_kernel<<<dim3((S + 8 * DITER - 1) / (8 * DITER), NB * NH), 256>>>(kcache, S, KV);
    topk_thresh<<<NROWS_ATT, 256>>>(S, nrem);
    attn_gather<<<dim3(NROWS_ATT, VSPLIT), 256>>>(vcache, S, KV);
    proj_out<<<dim3(DMODEL / 1024, KSPLIT), 256>>>(Wo, out);
}

// round 14
// speedup vs baseline: 1.9330x; 1.0863x over previous
#include <cuda_runtime.h>
#include <math.h>

#define NB 2
#define NQ 4
#define NH 32
#define NHK 8
#define HD 128
#define DMODEL 4096
#define NCOLS (DMODEL + 1024 + 1024)   // 6144 fused qkv output columns
#define NROWS (NB * NQ)                // 8
#define SMAX 4352
#define NROWS_ATT (NB * NH * NQ)       // 256
#define KSPLIT 64
#define KCH (DMODEL / KSPLIT)          // 64
#define VSPLIT 8
#define DITER 4                        // draft: key rows per warp

// vector reduction: 4x fewer L2 atomics than scalar atomicAdd
__device__ __forceinline__ void red_add_v4(float* p, float4 v) {
    asm volatile("red.global.add.v4.f32 [%0], {%1,%2,%3,%4};"
                 :: "l"(p), "f"(v.x), "f"(v.y), "f"(v.z), "f"(v.w) : "memory");
}

// ---------------- scratch (device globals; no allocation) ----------------
__device__ float g_qkv[NROWS * NCOLS];
__device__ float g_cos[SMAX * 64];
__device__ float g_sin[SMAX * 64];
__device__ float g_qr[NB * NH * NQ * HD];
__device__ float g_knew[NB * NHK * NQ * HD];
__device__ float g_vnew[NB * NHK * NQ * HD];
__device__ float g_draft[NROWS_ATT * SMAX];
__device__ unsigned int g_thrkey[NROWS_ATT];
__device__ float g_rowmax[NROWS_ATT];
__device__ float g_num[NROWS_ATT * HD];
__device__ float g_den[NROWS_ATT];

// ---------------- init: zero accumulators + rope tables in one kernel ----------------
__global__ void init_kernel(float* __restrict__ out, int osz, int zb, int S) {
    if ((int)blockIdx.x < zb) {
        int i = blockIdx.x * 256 + threadIdx.x;
        if (i < NROWS * NCOLS)   g_qkv[i] = 0.f;
        if (i < NROWS_ATT * HD)  g_num[i] = 0.f;
        if (i < NROWS_ATT)       g_den[i] = 0.f;
        if (i < osz)             out[i]  = 0.f;
        return;
    }
    __shared__ float invf[64];
    int t = threadIdx.x;
    if (t < 64) {
        double x = (double)t / 64.0;
        double p = exp(x * 9.210340371976184);   // ln(10000)
        invf[t] = 1.0f / (float)p;
    }
    __syncthreads();
    int pos = (blockIdx.x - zb) * 4 + (t >> 6);
    int i = t & 63;
    if (pos < S) {
        float arg = (float)pos * invf[i];
        double a = (double)arg;
        double k = rint(a * 0.15915494309189535);
        float r = (float)(a - k * 6.283185307179586);
        float s, c;
        __sincosf(r, &s, &c);
        g_cos[pos * 64 + i] = c;
        g_sin[pos * 64 + i] = s;
    }
}

// ---------------- fused QKV projection: 4 cols/thread, KSPLIT=64 ----------------
// grid: (NCOLS/1024, KSPLIT), block 256
__global__ void __launch_bounds__(256) proj_qkv(const float* __restrict__ hid,
                                                const float* __restrict__ Wq,
                                                const float* __restrict__ Wk,
                                                const float* __restrict__ Wv) {
    __shared__ float hs[NROWS][KCH];
    int t = threadIdx.x;
    int j = (blockIdx.x * 256 + t) * 4;
    int k0 = blockIdx.y * KCH;
    if (t < NROWS * KCH / 4) {
        int r = t / (KCH / 4), c4 = t % (KCH / 4);
        *(float4*)&hs[r][c4 * 4] = *(const float4*)&hid[r * DMODEL + k0 + c4 * 4];
    }
    __syncthreads();

    const float* W; int ncol; int jj;
    if (j < DMODEL)             { W = Wq; ncol = DMODEL; jj = j; }
    else if (j < DMODEL + 1024) { W = Wk; ncol = 1024;   jj = j - DMODEL; }
    else                        { W = Wv; ncol = 1024;   jj = j - DMODEL - 1024; }

    float4 acc[NROWS];
#pragma unroll
    for (int r = 0; r < NROWS; r++) acc[r] = make_float4(0.f, 0.f, 0.f, 0.f);
    const float* wp = W + (size_t)k0 * ncol + jj;
#pragma unroll 8
    for (int k = 0; k < KCH; k++) {
        float4 w4 = *(const float4*)(wp + (size_t)k * ncol);
#pragma unroll
        for (int r = 0; r < NROWS; r++) {
            float h = hs[r][k];
            acc[r].x += h * w4.x; acc[r].y += h * w4.y;
            acc[r].z += h * w4.z; acc[r].w += h * w4.w;
        }
    }
#pragma unroll
    for (int r = 0; r < NROWS; r++)
        red_add_v4(&g_qkv[r * NCOLS + j], acc[r]);
}

// ---------------- rope new q/k, copy v (float4 pair tasks) ----------------
// tasks = NB*NH*NQ*16 = 4096 -> 16 blocks x 256
__global__ void rope_qkv(int S) {
    int idx = blockIdx.x * 256 + threadIdx.x;
    int c = (idx & 15) * 4;
    int q = (idx >> 4) & 3;
    int h = (idx >> 6) & 31;
    int b = idx >> 11;
    int pos = S - NQ + q;
    int row = b * NQ + q;
    float4 cv = *(const float4*)&g_cos[pos * 64 + c];
    float4 sv = *(const float4*)&g_sin[pos * 64 + c];
    const float* base = g_qkv + row * NCOLS;
    {
        float4 xl = *(const float4*)(base + h * HD + c);
        float4 xh = *(const float4*)(base + h * HD + c + 64);
        float4 lo, hi;
        lo.x = xl.x * cv.x - xh.x * sv.x;  hi.x = xh.x * cv.x + xl.x * sv.x;
        lo.y = xl.y * cv.y - xh.y * sv.y;  hi.y = xh.y * cv.y + xl.y * sv.y;
        lo.z = xl.z * cv.z - xh.z * sv.z;  hi.z = xh.z * cv.z + xl.z * sv.z;
        lo.w = xl.w * cv.w - xh.w * sv.w;  hi.w = xh.w * cv.w + xl.w * sv.w;
        float* qo = g_qr + ((b * NH + h) * NQ + q) * HD;
        *(float4*)(qo + c) = lo; *(float4*)(qo + c + 64) = hi;
    }
    if (h < NHK) {
        const float* kb = base + DMODEL + h * HD;
        float4 xl = *(const float4*)(kb + c);
        float4 xh = *(const float4*)(kb + c + 64);
        float4 lo, hi;
        lo.x = xl.x * cv.x - xh.x * sv.x;  hi.x = xh.x * cv.x + xl.x * sv.x;
        lo.y = xl.y * cv.y - xh.y * sv.y;  hi.y = xh.y * cv.y + xl.y * sv.y;
        lo.z = xl.z * cv.z - xh.z * sv.z;  hi.z = xh.z * cv.z + xl.z * sv.z;
        lo.w = xl.w * cv.w - xh.w * sv.w;  hi.w = xh.w * cv.w + xl.w * sv.w;
        float* ko = g_knew + ((b * NHK + h) * NQ + q) * HD;
        *(float4*)(ko + c) = lo; *(float4*)(ko + c + 64) = hi;
        const float* vb = base + DMODEL + 1024 + h * HD;
        float* vo = g_vnew + ((b * NHK + h) * NQ + q) * HD;
        *(float4*)(vo + c)      = *(const float4*)(vb + c);
        *(float4*)(vo + c + 64) = *(const float4*)(vb + c + 64);
    }
}

// ---------------- draft scores: warp-per-key-row, prefetched K, 6-shuffle reduce ----------------
// grid: (ceil(S/(8*DITER)), NB*NH), block 256 = 8 warps
__global__ void __launch_bounds__(256) draft_kernel(const float* __restrict__ kcache,
                                                    int S, int KV) {
    int bh = blockIdx.y;
    int b = bh >> 5, h = bh & 31;
    int lane = threadIdx.x & 31, warp = threadIdx.x >> 5;
    const unsigned int FULL = 0xffffffffu;

    // q in registers: lane l holds q[q][4l..4l+3]
    float4 qreg[NQ];
    const float* qp = &g_qr[(size_t)bh * NQ * HD + lane * 4];
#pragma unroll
    for (int q = 0; q < NQ; q++) qreg[q] = *(const float4*)(qp + q * HD);

    int sbase = blockIdx.x * (8 * DITER) + warp;
    float sign = (lane < 16) ? -1.f : 1.f;

    // Phase 1: prefetch all DITER key rows (MLP = DITER per warp)
    float4 kx[DITER];
#pragma unroll
    for (int it = 0; it < DITER; it++) {
        int s = sbase + it * 8;
        if (s < KV) {
            kx[it] = *(const float4*)&kcache[((size_t)bh * KV + s) * HD + lane * 4];
        } else if (s < S) {
            kx[it] = *(const float4*)&g_knew[(((b * NHK + (h >> 2)) * NQ) + (s - KV)) * HD + lane * 4];
        } else {
            kx[it] = make_float4(0.f, 0.f, 0.f, 0.f);
        }
    }

    // Phase 2: rope + dot + transposed reduce per row
#pragma unroll
    for (int it = 0; it < DITER; it++) {
        int s = sbase + it * 8;
        if (s >= S) break;                 // warp-uniform exit
        float4 kr = kx[it];
        if (s < KV) {
            float4 cv = *(const float4*)&g_cos[s * 64 + (lane & 15) * 4];
            float4 sv = *(const float4*)&g_sin[s * 64 + (lane & 15) * 4];
            // fold per-lane sign into sin factor (constant across iterations)
            sv.x *= sign; sv.y *= sign; sv.z *= sign; sv.w *= sign;
            float ox = __shfl_xor_sync(FULL, kr.x, 16);
            float oy = __shfl_xor_sync(FULL, kr.y, 16);
            float oz = __shfl_xor_sync(FULL, kr.z, 16);
            float ow = __shfl_xor_sync(FULL, kr.w, 16);
            kr.x = kr.x * cv.x + ox * sv.x;
            kr.y = kr.y * cv.y + oy * sv.y;
            kr.z = kr.z * cv.z + oz * sv.z;
            kr.w = kr.w * cv.w + ow * sv.w;
        }
        float a0 = kr.x * qreg[0].x + kr.y * qreg[0].y + kr.z * qreg[0].z + kr.w * qreg[0].w;
        float a1 = kr.x * qreg[1].x + kr.y * qreg[1].y + kr.z * qreg[1].z + kr.w * qreg[1].w;
        float a2 = kr.x * qreg[2].x + kr.y * qreg[2].y + kr.z * qreg[2].z + kr.w * qreg[2].w;
        float a3 = kr.x * qreg[3].x + kr.y * qreg[3].y + kr.z * qreg[3].z + kr.w * qreg[3].w;

        // transposed warp reduction: 6 shuffles total.
        // level 1 (xor 1): (a0,a1)->v01, (a2,a3)->v23; keep q=lane&1 flavor
        bool b0 = (lane & 1);
        float keep01 = b0 ? a1 : a0, give01 = b0 ? a0 : a1;
        float v01 = keep01 + __shfl_xor_sync(FULL, give01, 1);
        float keep23 = b0 ? a3 : a2, give23 = b0 ? a2 : a3;
        float v23 = keep23 + __shfl_xor_sync(FULL, give23, 1);
        // level 2 (xor 2): keep q = lane&3 flavor
        bool b1 = (lane & 2);
        float keep = b1 ? v23 : v01, give = b1 ? v01 : v23;
        float v = keep + __shfl_xor_sync(FULL, give, 2);
        // levels 3-5: plain butterflies within lane-class
        v += __shfl_xor_sync(FULL, v, 4);
        v += __shfl_xor_sync(FULL, v, 8);
        v += __shfl_xor_sync(FULL, v, 16);
        // lane l (l<4) holds full dot for q = l
        if (lane < 4)
            g_draft[(size_t)(bh * NQ + lane) * S + s] = v;
    }
}

// ---------------- per-row top-k threshold: 4-level radix select ----------------
__global__ void __launch_bounds__(256) topk_thresh(int S, int nrem) {
    __shared__ unsigned int keys[SMAX];
    __shared__ int hist[256];
    __shared__ float wmax[8];
    __shared__ unsigned int s_prefix;
    __shared__ int s_need;
    int row = blockIdx.x;
    const float* dr = &g_draft[(size_t)row * S];
    int t = threadIdx.x, lane = t & 31, warp = t >> 5;

    float mx = -3.4e38f;
    for (int i = t; i < S; i += 256) {
        float v = dr[i];
        mx = fmaxf(mx, v);
        unsigned int u = __float_as_uint(v);
        keys[i] = (u & 0x80000000u) ? ~u : (u | 0x80000000u);
    }
#pragma unroll
    for (int o = 16; o; o >>= 1) mx = fmaxf(mx, __shfl_xor_sync(0xffffffffu, mx, o));
    if (lane == 0) wmax[warp] = mx;
    __syncthreads();
    if (t == 0) {
        float m = wmax[0];
#pragma unroll
        for (int w = 1; w < 8; w++) m = fmaxf(m, wmax[w]);
        g_rowmax[row] = m;
    }

    unsigned int prefix = 0u;
    int need = nrem;
    for (int level = 3; level >= 0; level--) {
        hist[t] = 0;
        __syncthreads();
        int shift = level * 8;
        unsigned int pmask = (level == 3) ? 0u : (0xFFFFFFFFu << (shift + 8));
        for (int i = t; i < S; i += 256) {
            unsigned int k = keys[i];
            if ((k & pmask) == prefix) atomicAdd(&hist[(k >> shift) & 255], 1);
        }
        __syncthreads();
        if (t == 0) {
            int cum = 0, d = 255;
            for (; d > 0; d--) { cum += hist[d]; if (cum >= need) break; }
            if (cum < need) { cum += hist[0]; d = 0; }
            s_need = need - (cum - hist[d]);
            s_prefix = prefix | ((unsigned int)d << shift);
        }
        __syncthreads();
        prefix = s_prefix; need = s_need;
        __syncthreads();
    }
    if (t == 0) g_thrkey[row] = prefix;
}

// ---------------- sparse softmax * V gather (float4, 8 i-groups) ----------------
// grid: (NROWS_ATT, VSPLIT), block 256 = 8 groups x 32 lanes
__global__ void __launch_bounds__(256) attn_gather(const float* __restrict__ vcache,
                                                   int S, int KV) {
    __shared__ int sidx[512];
    __shared__ float sw[512];
    __shared__ int cnt;
    __shared__ float4 sacc[8][32];
    __shared__ float wden[8];
    int row = blockIdx.x;
    int bh = row >> 2;
    int b = bh >> 5, h = bh & 31;
    int chunk = (S + VSPLIT - 1) / VSPLIT;
    int s0 = blockIdx.y * chunk;
    int s1 = min(S, s0 + chunk);
    int t = threadIdx.x;
    if (t == 0) cnt = 0;
    __syncthreads();

    unsigned int thr = g_thrkey[row];
    float mx = g_rowmax[row];
    const float* dr = &g_draft[(size_t)row * S];
    for (int s = s0 + t; s < s1; s += 256) {
        float v = dr[s];
        unsigned int u = __float_as_uint(v);
        unsigned int key = (u & 0x80000000u) ? ~u : (u | 0x80000000u);
        if (key >= thr) {
            int p = atomicAdd(&cnt, 1);
            if (p < 512) {
                sidx[p] = s;
                sw[p] = __expf((v - mx) * 0.08838834764831843f);  // 1/sqrt(128)
            }
        }
    }
    __syncthreads();
    int n = min(cnt, 512);
    int hk = h >> 2;
    int g = t >> 5, lane = t & 31;
    float4 acc = make_float4(0.f, 0.f, 0.f, 0.f);
    for (int i = g; i < n; i += 8) {
        int s = sidx[i];
        float w = sw[i];
        const float* vp = (s < KV)
            ? &vcache[((size_t)bh * KV + s) * HD]
            : &g_vnew[(((b * NHK + hk) * NQ) + (s - KV)) * HD];
        float4 v4 = *(const float4*)(vp + lane * 4);
        acc.x += w * v4.x; acc.y += w * v4.y;
        acc.z += w * v4.z; acc.w += w * v4.w;
    }
    sacc[g][lane] = acc;
    __syncthreads();
    if (t < 32) {
        float4 sum = sacc[0][t];
#pragma unroll
        for (int gg = 1; gg < 8; gg++) {
            float4 a = sacc[gg][t];
            sum.x += a.x; sum.y += a.y; sum.z += a.z; sum.w += a.w;
        }
        red_add_v4(&g_num[row * HD + t * 4], sum);
    }

    float dsum = 0.f;
    for (int i = t; i < n; i += 256) dsum += sw[i];
#pragma unroll
    for (int o = 16; o; o >>= 1) dsum += __shfl_xor_sync(0xffffffffu, dsum, o);
    if ((t & 31) == 0) wden[t >> 5] = dsum;
    __syncthreads();
    if (t == 0) {
        float s8 = 0.f;
#pragma unroll
        for (int w = 0; w < 8; w++) s8 += wden[w];
        atomicAdd(&g_den[row], s8);
    }
}

// ---------------- output projection (finalize fused into tile load) ----------------
// grid: (DMODEL/1024, KSPLIT), block 256, 4 cols/thread
__global__ void __launch_bounds__(256) proj_out(const float* __restrict__ Wo,
                                                float* __restrict__ out) {
    __shared__ float hs[NROWS][KCH];
    int t = threadIdx.x;
    int j = (blockIdx.x * 256 + t) * 4;
    int k0 = blockIdx.y * KCH;
    if (t < NROWS * KCH / 4) {
        int r = t / (KCH / 4);              // r = b*NQ + q
        int kg = k0 + (t % (KCH / 4)) * 4;
        int b = r >> 2, q = r & 3;
        int h = kg >> 7, d = kg & 127;
        int row2 = ((b * NH + h) * NQ + q);
        float4 v = *(const float4*)&g_num[row2 * HD + d];
        float inv = 1.0f / g_den[row2];
        v.x *= inv; v.y *= inv; v.z *= inv; v.w *= inv;
        *(float4*)&hs[r][kg - k0] = v;
    }
    __syncthreads();

    float4 acc[NROWS];
#pragma unroll
    for (int r = 0; r < NROWS; r++) acc[r] = make_float4(0.f, 0.f, 0.f, 0.f);
    const float* wp = Wo + (size_t)k0 * DMODEL + j;
#pragma unroll 8
    for (int k = 0; k < KCH; k++) {
        float4 w4 = *(const float4*)(wp + (size_t)k * DMODEL);
#pragma unroll
        for (int r = 0; r < NROWS; r++) {
            float h = hs[r][k];
            acc[r].x += h * w4.x; acc[r].y += h * w4.y;
            acc[r].z += h * w4.z; acc[r].w += h * w4.w;
        }
    }
#pragma unroll
    for (int r = 0; r < NROWS; r++)
        red_add_v4(&out[r * DMODEL + j], acc[r]);
}

// ---------------- launcher ----------------
extern "C" void kernel_launch(void* const* d_in, const int* in_sizes, int n_in,
                              void* d_out, int out_size) {
    const float* hid    = (const float*)d_in[0];
    const float* kcache = (const float*)d_in[1];
    const float* vcache = (const float*)d_in[2];
    const float* Wq     = (const float*)d_in[3];
    const float* Wk     = (const float*)d_in[4];
    const float* Wv     = (const float*)d_in[5];
    const float* Wo     = (const float*)d_in[6];
    float* out = (float*)d_out;

    int KV = in_sizes[1] / (NB * NH * HD);
    int S = KV + NQ;
    if (S > SMAX) S = SMAX;
    int mo = S - (int)((double)S * 0.9);
    int cap = (S < 128) ? S : 128;
    int nrem = (cap > mo) ? cap : mo;
    if (nrem > 500) nrem = 500;

    int zmax = NROWS * NCOLS;
    if (out_size > zmax) zmax = out_size;
    int zb = (zmax + 255) / 256;
    int rb = (S + 3) / 4;
    init_kernel<<<zb + rb, 256>>>(out, out_size, zb, S);
    proj_qkv<<<dim3(NCOLS / 1024, KSPLIT), 256>>>(hid, Wq, Wk, Wv);
    rope_qkv<<<16, 256>>>(S);
    draft_kernel<<<dim3((S + 8 * DITER - 1) / (8 * DITER), NB * NH), 256>>>(kcache, S, KV);
    topk_thresh<<<NROWS_ATT, 256>>>(S, nrem);
    attn_gather<<<dim3(NROWS_ATT, VSPLIT), 256>>>(vcache, S, KV);
    proj_out<<<dim3(DMODEL / 1024, KSPLIT), 256>>>(Wo, out);
}